// round 7
// baseline (speedup 1.0000x reference)
#include <cuda_runtime.h>
#include <cuda_fp16.h>
#include <math.h>
#include <stdint.h>

// Problem constants (dataset shapes)
#define BMAX 4
#define SMAX 4096
#define DMAX 1024
#define EMAX 8
#define PPART 32          // partial-sum parts for column mean
#define NCH   32          // scan chunks  (L = SMAX/NCH = 128 = CTA_M)

// ---------------- scratch (device globals: no allocation allowed) ----------
__device__ __half g_x  [(size_t)BMAX*SMAX*DMAX];        // normed input (fp16)
__device__ float  g_hg [(size_t)BMAX*SMAX*2*DMAX];      // (c,v) float2 pairs
__device__ __half g_h  [(size_t)BMAX*SMAX*DMAX];        // recurrence output (fp16)
__device__ __half g_Wi [(size_t)BMAX*DMAX*2*DMAX];      // Wi^T [B][2D][D] K-major, interleaved
__device__ __half g_Wo [(size_t)BMAX*DMAX*DMAX];        // Wo^T [B][D][D]  K-major
__device__ float  g_part[(size_t)PPART*BMAX*DMAX];
__device__ float  g_probs[(size_t)BMAX*EMAX];
__device__ float  g_Ach [(size_t)BMAX*NCH*DMAX];
__device__ float  g_Ych [(size_t)BMAX*NCH*DMAX];
__device__ float  g_hin [(size_t)BMAX*NCH*DMAX];

// ---------------- helpers ---------------------------------------------------
__device__ __forceinline__ float rcp_fast(float x) {
    float r;
    asm("rcp.approx.ftz.f32 %0, %1;" : "=f"(r) : "f"(x));
    return r;
}
__device__ __forceinline__ uint32_t smem_u32(const void* p) {
    uint32_t a;
    asm("{ .reg .u64 t; cvta.to.shared.u64 t, %1; cvt.u32.u64 %0, t; }"
        : "=r"(a) : "l"(p));
    return a;
}
__device__ __forceinline__ void cp16(uint32_t dst, const void* src) {
    asm volatile("cp.async.cg.shared.global [%0], [%1], 16;"
                 :: "r"(dst), "l"(src) : "memory");
}
__device__ __forceinline__ uint32_t lds32(uint32_t a) {
    uint32_t v;
    asm volatile("ld.shared.b32 %0, [%1];" : "=r"(v) : "r"(a));
    return v;
}

// ---------------- RMSNorm: one block per (b,s) row, fp16 out ---------------
__global__ void rmsnorm_kernel(const float* __restrict__ inp,
                               const float* __restrict__ w, int D)
{
    long row = blockIdx.x;
    const float4* in4 = (const float4*)(inp + row*(long)D);
    __half2* xo2 = (__half2*)(g_x + row*(long)D);
    const float4* w4  = (const float4*)w;

    int tid = threadIdx.x;
    int n4  = D >> 2;
    float ss = 0.f;
    for (int i = tid; i < n4; i += blockDim.x) {
        float4 t = in4[i];
        ss += t.x*t.x + t.y*t.y + t.z*t.z + t.w*t.w;
    }
    for (int o = 16; o > 0; o >>= 1) ss += __shfl_xor_sync(0xffffffffu, ss, o);
    __shared__ float red[8];
    int warp = tid >> 5, lane = tid & 31;
    if (lane == 0) red[warp] = ss;
    __syncthreads();
    int nwarp = blockDim.x >> 5;
    __shared__ float s_r;
    if (tid == 0) {
        float tot = 0.f;
        for (int i = 0; i < nwarp; i++) tot += red[i];
        s_r = rsqrtf(tot / (float)D + 1e-6f);
    }
    __syncthreads();
    float r = s_r;
    for (int i = tid; i < n4; i += blockDim.x) {
        float4 t = in4[i];
        float4 ww = w4[i];
        xo2[i*2 + 0] = __floats2half2_rn(t.x * r * ww.x, t.y * r * ww.y);
        xo2[i*2 + 1] = __floats2half2_rn(t.z * r * ww.z, t.w * r * ww.w);
    }
}

// ---------------- column mean over S, stage 1 (reads fp16 x) ---------------
__global__ void colsum_partial_kernel(int B, int S, int D)
{
    int g = blockIdx.x * blockDim.x + threadIdx.x;
    int total = PPART * B * D;
    if (g >= total) return;
    int d = g % D;
    int b = (g / D) % B;
    int p = g / (D * B);
    int chunk = S / PPART;
    long base = ((long)b * S + (long)p * chunk) * D + d;
    float s = 0.f;
    for (int i = 0; i < chunk; i++) s += __half2float(g_x[base + (long)i * D]);
    g_part[g] = s;
}

// ------- fused: colsum finalize + router logits + softmax (1 block) --------
__global__ void router_fused_kernel(const float* __restrict__ rw,
                                    int B, int S, int D, int E)
{
    __shared__ float sxm[BMAX * DMAX];      // 16 KB
    __shared__ float slog[BMAX * EMAX];
    int tid = threadIdx.x;                  // 1024 threads
    for (int i = tid; i < B * D; i += blockDim.x) {
        float s = 0.f;
        for (int p = 0; p < PPART; p++) s += g_part[p * B * D + i];
        sxm[i] = s / (float)S;
    }
    __syncthreads();
    int w = tid >> 5, lane = tid & 31;
    if (w < B * E) {
        int b = w / E, e = w % E;
        float s = 0.f;
        for (int d = lane; d < D; d += 32)
            s += sxm[b * D + d] * rw[(long)d * E + e];
        for (int o = 16; o > 0; o >>= 1) s += __shfl_xor_sync(0xffffffffu, s, o);
        if (lane == 0) slog[w] = s;
    }
    __syncthreads();
    if (tid < (unsigned)B) {
        int b = tid;
        float m = -1e30f;
        for (int e = 0; e < E; e++) m = fmaxf(m, slog[b * E + e]);
        float sum = 0.f, p[EMAX];
        for (int e = 0; e < E; e++) { p[e] = expf(slog[b * E + e] - m); sum += p[e]; }
        float inv = 1.f / sum;
        for (int e = 0; e < E; e++) g_probs[b * E + e] = p[e] * inv;
    }
}

// ------- expert mixing + transpose, all batches per tile load --------------
// w: [E][Dk][Dn] (n contiguous). dst: [B][Dn][Dk] (k contiguous, fp16).
// interleave!=0: output row n -> 2*(n%Dh) + n/Dh   (pairs hidden/gate cols)
__global__ void combineT_kernel(const float* __restrict__ w,
                                __half* __restrict__ dst,
                                int B, int E, int Dk, int Dn,
                                int interleave, int Dh)
{
    __shared__ float ts[32][33];
    __shared__ float sp[BMAX * EMAX];
    if (threadIdx.x < (unsigned)(B * E)) sp[threadIdx.x] = g_probs[threadIdx.x];
    __syncthreads();
    int k0 = blockIdx.x * 32, n0 = blockIdx.y * 32;
    int tk = threadIdx.x >> 3;        // 0..31
    int tn4 = threadIdx.x & 7;        // 0..7
    int tn = tk, tk4 = tn4;           // roles for write phase

    float4 t[EMAX];
    {
        const float* base = w + (long)(k0 + tk) * Dn + n0 + tn4 * 4;
        long estride = (long)Dk * Dn;
#pragma unroll
        for (int e = 0; e < EMAX; e++)
            t[e] = *(const float4*)(base + e * estride);
    }
    for (int b = 0; b < B; b++) {
        float4 acc = {0.f, 0.f, 0.f, 0.f};
#pragma unroll
        for (int e = 0; e < EMAX; e++) {
            float p = sp[b * EMAX + e];
            acc.x = fmaf(p, t[e].x, acc.x); acc.y = fmaf(p, t[e].y, acc.y);
            acc.z = fmaf(p, t[e].z, acc.z); acc.w = fmaf(p, t[e].w, acc.w);
        }
        ts[tk][tn4 * 4 + 0] = acc.x;
        ts[tk][tn4 * 4 + 1] = acc.y;
        ts[tk][tn4 * 4 + 2] = acc.z;
        ts[tk][tn4 * 4 + 3] = acc.w;
        __syncthreads();
        int nrow = n0 + tn;
        if (interleave) nrow = 2 * (nrow % Dh) + (nrow / Dh);
        __half2 h01 = __floats2half2_rn(ts[tk4 * 4 + 0][tn], ts[tk4 * 4 + 1][tn]);
        __half2 h23 = __floats2half2_rn(ts[tk4 * 4 + 2][tn], ts[tk4 * 4 + 3][tn]);
        __half2* dp = (__half2*)(dst + ((long)b * Dn + nrow) * Dk + k0 + tk4 * 4);
        dp[0] = h01;
        dp[1] = h23;
        __syncthreads();
    }
}

// ---------------- gating scalar ---------------------------------------------
__device__ __forceinline__ void cv_one(float hid, float gate, float& c, float& v)
{
    float t = __expf(-fabsf(gate));
    float r = rcp_fast(1.f + t);
    float sg, cc;
    if (gate >= 0.f) { sg = r;      cc = t * r; }
    else             { sg = t * r;  cc = r;     }
    float gg;
    if (hid >= 0.f) gg = hid + 0.5f;
    else {
        float t2 = __expf(hid);
        gg = t2 * rcp_fast(1.f + t2);
    }
    c = cc;
    v = sg * gg;
}

// ---------------- fp16 mma.sync GEMM, cp.async 3-stage, 2 CTAs/SM ----------
// A: [M][K] K-major fp16.  Bt: [N][K] K-major fp16.  fp32 accumulate.
// CTA tile 128x128, 8 warps (2x4) of 64x32. BK=64 (rows = 128 bytes).
// MODE 0: Cout = A@Bt^T + resid (fp32).
// MODE 1: (hidden,gate)->(c,v) pairs + in-CTA chunk scan (tile M == chunk L).
#define STAGES 3
#define CTA_M 128
#define CTA_N 128
#define GBK 64
#define A_BYTES (CTA_M * GBK * 2)                 // 16384
#define B_BYTES (CTA_N * GBK * 2)                 // 16384
#define STAGE_BYTES (A_BYTES + B_BYTES)           // 32768
#define GEMM_SMEM (STAGES * STAGE_BYTES + 1024)   // ~97.3 KB
#define ROWPAD 129                                // float2 per channel (pad)

template<int MODE>
__global__ void __launch_bounds__(256, 2)
tc_gemm(const __half* __restrict__ A, const __half* __restrict__ Bt,
        const float* __restrict__ resid, float* __restrict__ Cout,
        float2* __restrict__ cv,
        int M, int N, int K, long sA, long sB, long sC, int Dh, int S)
{
    extern __shared__ char dsm[];
    const uint32_t sb = (smem_u32(dsm) + 1023u) & ~1023u;

    const int bz = blockIdx.z;
    A  += (long)bz * sA;
    Bt += (long)bz * sB;

    const long tileM = (long)blockIdx.y * CTA_M;
    const long tileN = (long)blockIdx.x * CTA_N;
    const int tid  = threadIdx.x;
    const int warp = tid >> 5;
    const int lane = tid & 31;
    const int wm = (warp >> 2) * 64;   // 0,64
    const int wn = (warp & 3) * 32;    // 0..96
    const int grp = lane >> 2;         // 0..7
    const int tig = lane & 3;          // 0..3

    float acc[4][4][4];
#pragma unroll
    for (int i = 0; i < 4; i++)
#pragma unroll
        for (int j = 0; j < 4; j++)
#pragma unroll
            for (int r = 0; r < 4; r++) acc[i][j][r] = 0.f;

    auto fill_stage = [&](int stage, int ch) {
        uint32_t bAf = sb + stage * STAGE_BYTES;
        uint32_t bBf = bAf + A_BYTES;
        int k0 = ch * GBK;
#pragma unroll
        for (int j = 0; j < 4; j++) {
            int idx = j * 256 + tid;
            int row = idx >> 3, seg = idx & 7;
            uint32_t off = (uint32_t)(row * 128) + (uint32_t)((seg * 16) ^ ((row & 7) * 16));
            cp16(bAf + off, A + (tileM + row) * K + k0 + seg * 8);
        }
#pragma unroll
        for (int j = 0; j < 4; j++) {
            int idx = j * 256 + tid;
            int row = idx >> 3, seg = idx & 7;
            uint32_t off = (uint32_t)(row * 128) + (uint32_t)((seg * 16) ^ ((row & 7) * 16));
            cp16(bBf + off, Bt + (tileN + row) * K + k0 + seg * 8);
        }
        asm volatile("cp.async.commit_group;" ::: "memory");
    };

    const int nch = K / GBK;
    fill_stage(0, 0);
    fill_stage(1, 1);

    for (int ch = 0; ch < nch; ch++) {
        int st = ch % STAGES;
        asm volatile("cp.async.wait_group %0;" :: "n"(STAGES - 2) : "memory");
        __syncthreads();
        if (ch + 2 < nch) fill_stage((ch + 2) % STAGES, ch + 2);
        else asm volatile("cp.async.commit_group;" ::: "memory");

        uint32_t bA = sb + st * STAGE_BYTES;
        uint32_t bB = bA + A_BYTES;
        uint32_t aRB0[4], aRB1[4], aMK[4];
#pragma unroll
        for (int mf = 0; mf < 4; mf++) {
            int m0 = wm + mf * 16 + grp;
            aRB0[mf] = bA + m0 * 128;
            aRB1[mf] = bA + (m0 + 8) * 128;
            aMK[mf] = (uint32_t)((m0 & 7) * 16);
        }
        uint32_t bRB[4], bMK[4];
#pragma unroll
        for (int nf = 0; nf < 4; nf++) {
            int n0 = wn + nf * 8 + grp;
            bRB[nf] = bB + n0 * 128;
            bMK[nf] = (uint32_t)((n0 & 7) * 16);
        }
#pragma unroll
        for (int ks = 0; ks < 4; ks++) {
            uint32_t klo = (uint32_t)(ks * 32 + tig * 4);
            uint32_t khi = klo + 16;
            uint32_t af[4][4];
#pragma unroll
            for (int mf = 0; mf < 4; mf++) {
                af[mf][0] = lds32(aRB0[mf] + (klo ^ aMK[mf]));
                af[mf][1] = lds32(aRB1[mf] + (klo ^ aMK[mf]));
                af[mf][2] = lds32(aRB0[mf] + (khi ^ aMK[mf]));
                af[mf][3] = lds32(aRB1[mf] + (khi ^ aMK[mf]));
            }
            uint32_t bf[4][2];
#pragma unroll
            for (int nf = 0; nf < 4; nf++) {
                bf[nf][0] = lds32(bRB[nf] + (klo ^ bMK[nf]));
                bf[nf][1] = lds32(bRB[nf] + (khi ^ bMK[nf]));
            }
#pragma unroll
            for (int mf = 0; mf < 4; mf++)
#pragma unroll
                for (int nf = 0; nf < 4; nf++) {
                    asm volatile(
                        "mma.sync.aligned.m16n8k16.row.col.f32.f16.f16.f32 "
                        "{%0,%1,%2,%3},{%4,%5,%6,%7},{%8,%9},{%0,%1,%2,%3};"
                        : "+f"(acc[mf][nf][0]), "+f"(acc[mf][nf][1]),
                          "+f"(acc[mf][nf][2]), "+f"(acc[mf][nf][3])
                        : "r"(af[mf][0]), "r"(af[mf][1]), "r"(af[mf][2]), "r"(af[mf][3]),
                          "r"(bf[nf][0]), "r"(bf[nf][1]));
                }
        }
    }

    // ---- epilogue ----
    if (MODE == 0) {
        const float* rz = resid ? resid + (long)bz * sC : nullptr;
        float* czp = Cout + (long)bz * sC;
#pragma unroll
        for (int mf = 0; mf < 4; mf++) {
#pragma unroll
            for (int nf = 0; nf < 4; nf++) {
                long r0 = tileM + wm + mf * 16 + grp;
                long c  = tileN + wn + nf * 8 + 2 * tig;
                long i0 = r0 * N + c;
                long i1 = (r0 + 8) * N + c;
                float2 v0 = make_float2(acc[mf][nf][0], acc[mf][nf][1]);
                float2 v1 = make_float2(acc[mf][nf][2], acc[mf][nf][3]);
                if (rz) {
                    float2 q0 = *(const float2*)(rz + i0);
                    float2 q1 = *(const float2*)(rz + i1);
                    v0.x += q0.x; v0.y += q0.y;
                    v1.x += q1.x; v1.y += q1.y;
                }
                *(float2*)(czp + i0) = v0;
                *(float2*)(czp + i1) = v1;
            }
        }
    } else {
        // (c,v) to global + in-CTA chunk scan (this tile == one scan chunk)
        float2* cvb = cv + (long)bz * S * (long)Dh;
        float2* scv = (float2*)dsm;          // reuse stage smem: [ch 64][row 128+pad]
        __syncthreads();                      // everyone done reading stage smem
#pragma unroll
        for (int mf = 0; mf < 4; mf++) {
#pragma unroll
            for (int nf = 0; nf < 4; nf++) {
                int rl   = wm + mf * 16 + grp;              // local row 0..127
                int dloc = (wn >> 1) + nf * 4 + tig;        // 0..63
                long r0 = tileM + rl;
                long d  = (tileN >> 1) + dloc;
                float cc, vv;
                cv_one(acc[mf][nf][0], acc[mf][nf][1], cc, vv);
                cvb[r0 * Dh + d] = make_float2(cc, vv);
                scv[dloc * ROWPAD + rl] = make_float2(cc, vv);
                cv_one(acc[mf][nf][2], acc[mf][nf][3], cc, vv);
                cvb[(r0 + 8) * Dh + d] = make_float2(cc, vv);
                scv[dloc * ROWPAD + rl + 8] = make_float2(cc, vv);
            }
        }
        __syncthreads();
        // 2 threads per channel, 64 rows each
        if (tid < 128) {
            int dloc = tid & 63;
            int half = tid >> 6;
            const float2* p = scv + dloc * ROWPAD + half * 64;
            float Aa = 1.f, Yy = 0.f;
#pragma unroll 8
            for (int i = 0; i < 64; i++) {
                float2 t = p[i];
                Aa *= t.x;
                Yy = fmaf(t.x, Yy, t.y);
            }
            scv[64 * ROWPAD + tid] = make_float2(Aa, Yy);
        }
        __syncthreads();
        if (tid < 64) {
            float2 p0 = scv[64 * ROWPAD + tid];        // rows 0..63
            float2 p1 = scv[64 * ROWPAD + 64 + tid];   // rows 64..127
            float Aa = p0.x * p1.x;
            float Yy = fmaf(p1.x, p0.y, p1.y);
            int chk = (int)(tileM >> 7);               // chunk index (L=128)
            int nchk = S >> 7;
            long d = (tileN >> 1) + tid;
            long idx = ((long)bz * nchk + chk) * (long)Dh + d;
            g_Ach[idx] = Aa;
            g_Ych[idx] = Yy;
        }
    }
}

// ---------------- chunked linear-recurrence scan (passes B, C) --------------
__global__ void scan_passB_kernel(const float* __restrict__ state,
                                  float* __restrict__ out,
                                  int B, int D, int nch,
                                  long outBase, long out_size)
{
    int g = blockIdx.x * blockDim.x + threadIdx.x;
    if (g >= B * D) return;
    int d = g % D, b = g / D;
    float h = state[b * D + d];
    for (int ch = 0; ch < nch; ch++) {
        int idx = (b * nch + ch) * D + d;
        g_hin[idx] = h;
        h = fmaf(g_Ach[idx], h, g_Ych[idx]);
    }
    if (out_size >= outBase + (long)B * D)
        out[outBase + (long)b * D + d] = h;          // new_state
    if (g == 0 && out_size >= outBase + (long)B * D + 1)
        out[outBase + (long)B * D] = 0.f;            // aux_loss
}

__global__ void scan_passC_kernel(int B, int S, int D, int L, int nch)
{
    int g = blockIdx.x * blockDim.x + threadIdx.x;
    int total = B * nch * D;
    if (g >= total) return;
    int d = g % D;
    int ch = (g / D) % nch;
    int b = g / (D * nch);
    const float2* cv = (const float2*)g_hg;
    long base = ((long)b * S + (long)ch * L) * D + d;
    float h = g_hin[g];
#pragma unroll 4
    for (int i = 0; i < 128; i++) {
        float2 t = cv[base + (long)i * D];
        h = fmaf(t.x, h, t.y);
        g_h[base + (long)i * D] = __float2half_rn(h);
    }
}

// ---------------- launch ----------------------------------------------------
extern "C" void kernel_launch(void* const* d_in, const int* in_sizes, int n_in,
                              void* d_out, int out_size)
{
    const float* inputs   = (const float*)d_in[0];
    // d_in[1]: attention_mask (unused by reference)
    const float* state    = (const float*)d_in[2];
    const float* normw    = (const float*)d_in[3];
    const float* router_w = (const float*)d_in[4];
    const float* w_in     = (const float*)d_in[5];
    const float* w_out    = (const float*)d_in[6];
    float* out = (float*)d_out;

    const int D = in_sizes[3];
    const int E = in_sizes[4] / D;
    const int B = in_sizes[2] / D;
    const int S = in_sizes[0] / (B * D);
    const int N2 = 2 * D;
    const int L = S / NCH;
    (void)L;

    __half *px, *ph, *pWi, *pWo;
    float *phg;
    cudaGetSymbolAddress((void**)&px,  g_x);
    cudaGetSymbolAddress((void**)&phg, g_hg);
    cudaGetSymbolAddress((void**)&ph,  g_h);
    cudaGetSymbolAddress((void**)&pWi, g_Wi);
    cudaGetSymbolAddress((void**)&pWo, g_Wo);

    cudaFuncSetAttribute(tc_gemm<0>, cudaFuncAttributeMaxDynamicSharedMemorySize, GEMM_SMEM);
    cudaFuncSetAttribute(tc_gemm<1>, cudaFuncAttributeMaxDynamicSharedMemorySize, GEMM_SMEM);

    // 1. RMSNorm (fp16 output)
    rmsnorm_kernel<<<B * S, 256>>>(inputs, normw, D);

    // 2. column partial sums
    {
        int total = PPART * B * D;
        colsum_partial_kernel<<<(total + 255) / 256, 256>>>(B, S, D);
    }

    // 3. fused colsum-final + router softmax
    router_fused_kernel<<<1, 1024>>>(router_w, B, S, D, E);

    // 4. expert-mixed transposed weights (fp16, all batches per tile)
    {
        dim3 gI(D / 32, N2 / 32);
        combineT_kernel<<<gI, 256>>>(w_in, pWi, B, E, D, N2, 1, D);   // interleaved
        dim3 gO(D / 32, D / 32);
        combineT_kernel<<<gO, 256>>>(w_out, pWo, B, E, D, D, 0, D);
    }

    // 5. GEMM1 (M=S, N=2D, K=D): gating -> (c,v) in g_hg + fused chunk-scan A
    {
        dim3 grid(N2 / CTA_N, S / CTA_M, B);
        tc_gemm<1><<<grid, 256, GEMM_SMEM>>>(px, pWi, nullptr, nullptr,
                                             (float2*)phg,
                                             S, N2, D,
                                             (long)S * D, (long)N2 * D, 0L,
                                             D, S);
    }

    // 6. scan passes B (chunk prefix) and C (within-chunk)
    {
        int totA = B * NCH * D;
        scan_passB_kernel<<<(B * D + 255) / 256, 256>>>(state, out, B, D, NCH,
                                                        (long)B * S * D, (long)out_size);
        scan_passC_kernel<<<(totA + 255) / 256, 256>>>(B, S, D, L, NCH);
    }

    // 7. GEMM2: out = h @ Wo^T + inputs   (M=S, N=D, K=D)
    {
        dim3 grid(D / CTA_N, S / CTA_M, B);
        tc_gemm<0><<<grid, 256, GEMM_SMEM>>>(ph, pWo, inputs, out,
                                             nullptr,
                                             S, D, D,
                                             (long)S * D, (long)D * D, (long)S * D,
                                             D, S);
    }
}

// round 8
// speedup vs baseline: 1.0677x; 1.0677x over previous
#include <cuda_runtime.h>
#include <cuda_fp16.h>
#include <math.h>
#include <stdint.h>

// Problem constants (dataset shapes)
#define BMAX 4
#define SMAX 4096
#define DMAX 1024
#define EMAX 8
#define PPART 32          // partial-sum parts for column mean
#define NCH   32          // scan chunks  (L = SMAX/NCH = 128)

// ---------------- scratch (device globals: no allocation allowed) ----------
__device__ __half  g_x  [(size_t)BMAX*SMAX*DMAX];       // normed input (fp16)
__device__ __half2 g_cv [(size_t)BMAX*SMAX*DMAX];       // packed (c,v) per element
__device__ __half  g_h  [(size_t)BMAX*SMAX*DMAX];       // recurrence output (fp16)
__device__ __half  g_Wi [(size_t)BMAX*DMAX*2*DMAX];     // Wi^T [B][2D][D] K-major, interleaved
__device__ __half  g_Wo [(size_t)BMAX*DMAX*DMAX];       // Wo^T [B][D][D]  K-major
__device__ float   g_part[(size_t)PPART*BMAX*DMAX];
__device__ float   g_probs[(size_t)BMAX*EMAX];
__device__ float   g_Ach [(size_t)BMAX*NCH*DMAX];
__device__ float   g_Ych [(size_t)BMAX*NCH*DMAX];
__device__ float   g_hin [(size_t)BMAX*NCH*DMAX];

// ---------------- helpers ---------------------------------------------------
__device__ __forceinline__ float rcp_fast(float x) {
    float r;
    asm("rcp.approx.ftz.f32 %0, %1;" : "=f"(r) : "f"(x));
    return r;
}
__device__ __forceinline__ uint32_t smem_u32(const void* p) {
    uint32_t a;
    asm("{ .reg .u64 t; cvta.to.shared.u64 t, %1; cvt.u32.u64 %0, t; }"
        : "=r"(a) : "l"(p));
    return a;
}
__device__ __forceinline__ void cp16(uint32_t dst, const void* src) {
    asm volatile("cp.async.cg.shared.global [%0], [%1], 16;"
                 :: "r"(dst), "l"(src) : "memory");
}
__device__ __forceinline__ uint32_t lds32(uint32_t a) {
    uint32_t v;
    asm volatile("ld.shared.b32 %0, [%1];" : "=r"(v) : "r"(a));
    return v;
}

// ---------------- RMSNorm: one block per (b,s) row, fp16 out ---------------
__global__ void rmsnorm_kernel(const float* __restrict__ inp,
                               const float* __restrict__ w, int D)
{
    long row = blockIdx.x;
    const float4* in4 = (const float4*)(inp + row*(long)D);
    __half2* xo2 = (__half2*)(g_x + row*(long)D);
    const float4* w4  = (const float4*)w;

    int tid = threadIdx.x;
    int n4  = D >> 2;
    float ss = 0.f;
    for (int i = tid; i < n4; i += blockDim.x) {
        float4 t = in4[i];
        ss += t.x*t.x + t.y*t.y + t.z*t.z + t.w*t.w;
    }
    for (int o = 16; o > 0; o >>= 1) ss += __shfl_xor_sync(0xffffffffu, ss, o);
    __shared__ float red[8];
    int warp = tid >> 5, lane = tid & 31;
    if (lane == 0) red[warp] = ss;
    __syncthreads();
    int nwarp = blockDim.x >> 5;
    __shared__ float s_r;
    if (tid == 0) {
        float tot = 0.f;
        for (int i = 0; i < nwarp; i++) tot += red[i];
        s_r = rsqrtf(tot / (float)D + 1e-6f);
    }
    __syncthreads();
    float r = s_r;
    for (int i = tid; i < n4; i += blockDim.x) {
        float4 t = in4[i];
        float4 ww = w4[i];
        xo2[i*2 + 0] = __floats2half2_rn(t.x * r * ww.x, t.y * r * ww.y);
        xo2[i*2 + 1] = __floats2half2_rn(t.z * r * ww.z, t.w * r * ww.w);
    }
}

// ---------------- column mean over S, stage 1 (reads fp16 x) ---------------
__global__ void colsum_partial_kernel(int B, int S, int D)
{
    int g = blockIdx.x * blockDim.x + threadIdx.x;
    int total = PPART * B * D;
    if (g >= total) return;
    int d = g % D;
    int b = (g / D) % B;
    int p = g / (D * B);
    int chunk = S / PPART;
    long base = ((long)b * S + (long)p * chunk) * D + d;
    float s = 0.f;
    for (int i = 0; i < chunk; i++) s += __half2float(g_x[base + (long)i * D]);
    g_part[g] = s;
}

// ------- fused: colsum finalize + router logits + softmax (1 block) --------
__global__ void router_fused_kernel(const float* __restrict__ rw,
                                    int B, int S, int D, int E)
{
    __shared__ float sxm[BMAX * DMAX];      // 16 KB
    __shared__ float slog[BMAX * EMAX];
    int tid = threadIdx.x;                  // 1024 threads
    for (int i = tid; i < B * D; i += blockDim.x) {
        float s = 0.f;
        for (int p = 0; p < PPART; p++) s += g_part[p * B * D + i];
        sxm[i] = s / (float)S;
    }
    __syncthreads();
    int w = tid >> 5, lane = tid & 31;
    if (w < B * E) {
        int b = w / E, e = w % E;
        float s = 0.f;
        for (int d = lane; d < D; d += 32)
            s += sxm[b * D + d] * rw[(long)d * E + e];
        for (int o = 16; o > 0; o >>= 1) s += __shfl_xor_sync(0xffffffffu, s, o);
        if (lane == 0) slog[w] = s;
    }
    __syncthreads();
    if (tid < (unsigned)B) {
        int b = tid;
        float m = -1e30f;
        for (int e = 0; e < E; e++) m = fmaxf(m, slog[b * E + e]);
        float sum = 0.f, p[EMAX];
        for (int e = 0; e < E; e++) { p[e] = expf(slog[b * E + e] - m); sum += p[e]; }
        float inv = 1.f / sum;
        for (int e = 0; e < E; e++) g_probs[b * E + e] = p[e] * inv;
    }
}

// ------- expert mixing + transpose, all batches per tile load --------------
// w: [E][Dk][Dn] (n contiguous). dst: [B][Dn][Dk] (k contiguous, fp16).
// interleave!=0: output row n -> 2*(n%Dh) + n/Dh   (pairs hidden/gate cols)
__global__ void combineT_kernel(const float* __restrict__ w,
                                __half* __restrict__ dst,
                                int B, int E, int Dk, int Dn,
                                int interleave, int Dh)
{
    __shared__ float ts[32][33];
    __shared__ float sp[BMAX * EMAX];
    if (threadIdx.x < (unsigned)(B * E)) sp[threadIdx.x] = g_probs[threadIdx.x];
    __syncthreads();
    int k0 = blockIdx.x * 32, n0 = blockIdx.y * 32;
    int tk = threadIdx.x >> 3;        // 0..31
    int tn4 = threadIdx.x & 7;        // 0..7
    int tn = tk, tk4 = tn4;           // roles for write phase

    float4 t[EMAX];
    {
        const float* base = w + (long)(k0 + tk) * Dn + n0 + tn4 * 4;
        long estride = (long)Dk * Dn;
#pragma unroll
        for (int e = 0; e < EMAX; e++)
            t[e] = *(const float4*)(base + e * estride);
    }
    for (int b = 0; b < B; b++) {
        float4 acc = {0.f, 0.f, 0.f, 0.f};
#pragma unroll
        for (int e = 0; e < EMAX; e++) {
            float p = sp[b * EMAX + e];
            acc.x = fmaf(p, t[e].x, acc.x); acc.y = fmaf(p, t[e].y, acc.y);
            acc.z = fmaf(p, t[e].z, acc.z); acc.w = fmaf(p, t[e].w, acc.w);
        }
        ts[tk][tn4 * 4 + 0] = acc.x;
        ts[tk][tn4 * 4 + 1] = acc.y;
        ts[tk][tn4 * 4 + 2] = acc.z;
        ts[tk][tn4 * 4 + 3] = acc.w;
        __syncthreads();
        int nrow = n0 + tn;
        if (interleave) nrow = 2 * (nrow % Dh) + (nrow / Dh);
        __half2 h01 = __floats2half2_rn(ts[tk4 * 4 + 0][tn], ts[tk4 * 4 + 1][tn]);
        __half2 h23 = __floats2half2_rn(ts[tk4 * 4 + 2][tn], ts[tk4 * 4 + 3][tn]);
        __half2* dp = (__half2*)(dst + ((long)b * Dn + nrow) * Dk + k0 + tk4 * 4);
        dp[0] = h01;
        dp[1] = h23;
        __syncthreads();
    }
}

// ---------------- gating scalar ---------------------------------------------
__device__ __forceinline__ void cv_one(float hid, float gate, float& c, float& v)
{
    float t = __expf(-fabsf(gate));
    float r = rcp_fast(1.f + t);
    float sg, cc;
    if (gate >= 0.f) { sg = r;      cc = t * r; }
    else             { sg = t * r;  cc = r;     }
    float gg;
    if (hid >= 0.f) gg = hid + 0.5f;
    else {
        float t2 = __expf(hid);
        gg = t2 * rcp_fast(1.f + t2);
    }
    c = cc;
    v = sg * gg;
}

// ---------------- fp16 mma.sync GEMM, cp.async 3-stage, 2 CTAs/SM ----------
// A: [M][K] K-major fp16.  Bt: [N][K] K-major fp16.  fp32 accumulate.
// CTA tile 128x128, 8 warps (2x4) of 64x32. BK=64 (rows = 128 bytes).
// MODE 0: Cout = A@Bt^T + resid (fp32).
// MODE 1: (hidden,gate)->(c,v) packed half2.
#define STAGES 3
#define CTA_M 128
#define CTA_N 128
#define GBK 64
#define A_BYTES (CTA_M * GBK * 2)                 // 16384
#define B_BYTES (CTA_N * GBK * 2)                 // 16384
#define STAGE_BYTES (A_BYTES + B_BYTES)           // 32768
#define GEMM_SMEM (STAGES * STAGE_BYTES + 1024)   // ~97.3 KB

template<int MODE>
__global__ void __launch_bounds__(256, 2)
tc_gemm(const __half* __restrict__ A, const __half* __restrict__ Bt,
        const float* __restrict__ resid, float* __restrict__ Cout,
        __half2* __restrict__ cv,
        int M, int N, int K, long sA, long sB, long sC, int Dh, int S)
{
    extern __shared__ char dsm[];
    const uint32_t sb = (smem_u32(dsm) + 1023u) & ~1023u;

    const int bz = blockIdx.z;
    A  += (long)bz * sA;
    Bt += (long)bz * sB;

    const long tileM = (long)blockIdx.y * CTA_M;
    const long tileN = (long)blockIdx.x * CTA_N;
    const int tid  = threadIdx.x;
    const int warp = tid >> 5;
    const int lane = tid & 31;
    const int wm = (warp >> 2) * 64;   // 0,64
    const int wn = (warp & 3) * 32;    // 0..96
    const int grp = lane >> 2;         // 0..7
    const int tig = lane & 3;          // 0..3

    float acc[4][4][4];
#pragma unroll
    for (int i = 0; i < 4; i++)
#pragma unroll
        for (int j = 0; j < 4; j++)
#pragma unroll
            for (int r = 0; r < 4; r++) acc[i][j][r] = 0.f;

    auto fill_stage = [&](int stage, int ch) {
        uint32_t bAf = sb + stage * STAGE_BYTES;
        uint32_t bBf = bAf + A_BYTES;
        int k0 = ch * GBK;
#pragma unroll
        for (int j = 0; j < 4; j++) {
            int idx = j * 256 + tid;
            int row = idx >> 3, seg = idx & 7;
            uint32_t off = (uint32_t)(row * 128) + (uint32_t)((seg * 16) ^ ((row & 7) * 16));
            cp16(bAf + off, A + (tileM + row) * K + k0 + seg * 8);
        }
#pragma unroll
        for (int j = 0; j < 4; j++) {
            int idx = j * 256 + tid;
            int row = idx >> 3, seg = idx & 7;
            uint32_t off = (uint32_t)(row * 128) + (uint32_t)((seg * 16) ^ ((row & 7) * 16));
            cp16(bBf + off, Bt + (tileN + row) * K + k0 + seg * 8);
        }
        asm volatile("cp.async.commit_group;" ::: "memory");
    };

    const int nch = K / GBK;
    fill_stage(0, 0);
    fill_stage(1, 1);

    for (int ch = 0; ch < nch; ch++) {
        int st = ch % STAGES;
        asm volatile("cp.async.wait_group %0;" :: "n"(STAGES - 2) : "memory");
        __syncthreads();
        if (ch + 2 < nch) fill_stage((ch + 2) % STAGES, ch + 2);
        else asm volatile("cp.async.commit_group;" ::: "memory");

        uint32_t bA = sb + st * STAGE_BYTES;
        uint32_t bB = bA + A_BYTES;
        uint32_t aRB0[4], aRB1[4], aMK[4];
#pragma unroll
        for (int mf = 0; mf < 4; mf++) {
            int m0 = wm + mf * 16 + grp;
            aRB0[mf] = bA + m0 * 128;
            aRB1[mf] = bA + (m0 + 8) * 128;
            aMK[mf] = (uint32_t)((m0 & 7) * 16);
        }
        uint32_t bRB[4], bMK[4];
#pragma unroll
        for (int nf = 0; nf < 4; nf++) {
            int n0 = wn + nf * 8 + grp;
            bRB[nf] = bB + n0 * 128;
            bMK[nf] = (uint32_t)((n0 & 7) * 16);
        }
#pragma unroll
        for (int ks = 0; ks < 4; ks++) {
            uint32_t klo = (uint32_t)(ks * 32 + tig * 4);
            uint32_t khi = klo + 16;
            uint32_t af[4][4];
#pragma unroll
            for (int mf = 0; mf < 4; mf++) {
                af[mf][0] = lds32(aRB0[mf] + (klo ^ aMK[mf]));
                af[mf][1] = lds32(aRB1[mf] + (klo ^ aMK[mf]));
                af[mf][2] = lds32(aRB0[mf] + (khi ^ aMK[mf]));
                af[mf][3] = lds32(aRB1[mf] + (khi ^ aMK[mf]));
            }
            uint32_t bf[4][2];
#pragma unroll
            for (int nf = 0; nf < 4; nf++) {
                bf[nf][0] = lds32(bRB[nf] + (klo ^ bMK[nf]));
                bf[nf][1] = lds32(bRB[nf] + (khi ^ bMK[nf]));
            }
#pragma unroll
            for (int mf = 0; mf < 4; mf++)
#pragma unroll
                for (int nf = 0; nf < 4; nf++) {
                    asm volatile(
                        "mma.sync.aligned.m16n8k16.row.col.f32.f16.f16.f32 "
                        "{%0,%1,%2,%3},{%4,%5,%6,%7},{%8,%9},{%0,%1,%2,%3};"
                        : "+f"(acc[mf][nf][0]), "+f"(acc[mf][nf][1]),
                          "+f"(acc[mf][nf][2]), "+f"(acc[mf][nf][3])
                        : "r"(af[mf][0]), "r"(af[mf][1]), "r"(af[mf][2]), "r"(af[mf][3]),
                          "r"(bf[nf][0]), "r"(bf[nf][1]));
                }
        }
    }

    // ---- epilogue ----
    if (MODE == 0) {
        const float* rz = resid ? resid + (long)bz * sC : nullptr;
        float* czp = Cout + (long)bz * sC;
#pragma unroll
        for (int mf = 0; mf < 4; mf++) {
#pragma unroll
            for (int nf = 0; nf < 4; nf++) {
                long r0 = tileM + wm + mf * 16 + grp;
                long c  = tileN + wn + nf * 8 + 2 * tig;
                long i0 = r0 * N + c;
                long i1 = (r0 + 8) * N + c;
                float2 v0 = make_float2(acc[mf][nf][0], acc[mf][nf][1]);
                float2 v1 = make_float2(acc[mf][nf][2], acc[mf][nf][3]);
                if (rz) {
                    float2 q0 = *(const float2*)(rz + i0);
                    float2 q1 = *(const float2*)(rz + i1);
                    v0.x += q0.x; v0.y += q0.y;
                    v1.x += q1.x; v1.y += q1.y;
                }
                *(float2*)(czp + i0) = v0;
                *(float2*)(czp + i1) = v1;
            }
        }
    } else {
        __half2* cvb = cv + (long)bz * S * (long)Dh;
#pragma unroll
        for (int mf = 0; mf < 4; mf++) {
#pragma unroll
            for (int nf = 0; nf < 4; nf++) {
                long r0 = tileM + wm + mf * 16 + grp;
                long c  = tileN + wn + nf * 8 + 2 * tig;
                long d  = c >> 1;
                float cc, vv;
                cv_one(acc[mf][nf][0], acc[mf][nf][1], cc, vv);
                cvb[r0 * Dh + d] = __floats2half2_rn(cc, vv);
                cv_one(acc[mf][nf][2], acc[mf][nf][3], cc, vv);
                cvb[(r0 + 8) * Dh + d] = __floats2half2_rn(cc, vv);
            }
        }
    }
}

// ---------------- chunked linear-recurrence scan ---------------------------
__global__ void scan_passA_kernel(int B, int S, int D, int L, int nch)
{
    int g = blockIdx.x * blockDim.x + threadIdx.x;
    int total = B * nch * D;
    if (g >= total) return;
    int d = g % D;
    int ch = (g / D) % nch;
    int b = g / (D * nch);
    long base = ((long)b * S + (long)ch * L) * D + d;
    float A = 1.f, Y = 0.f;
#pragma unroll 4
    for (int i = 0; i < 128; i++) {
        float2 t = __half22float2(g_cv[base + (long)i * D]);
        A *= t.x;
        Y = fmaf(t.x, Y, t.y);
    }
    g_Ach[g] = A;
    g_Ych[g] = Y;
}

__global__ void scan_passB_kernel(const float* __restrict__ state,
                                  float* __restrict__ out,
                                  int B, int D, int nch,
                                  long outBase, long out_size)
{
    int g = blockIdx.x * blockDim.x + threadIdx.x;
    if (g >= B * D) return;
    int d = g % D, b = g / D;
    float h = state[b * D + d];
    for (int ch = 0; ch < nch; ch++) {
        int idx = (b * nch + ch) * D + d;
        g_hin[idx] = h;
        h = fmaf(g_Ach[idx], h, g_Ych[idx]);
    }
    if (out_size >= outBase + (long)B * D)
        out[outBase + (long)b * D + d] = h;          // new_state
    if (g == 0 && out_size >= outBase + (long)B * D + 1)
        out[outBase + (long)B * D] = 0.f;            // aux_loss
}

__global__ void scan_passC_kernel(int B, int S, int D, int L, int nch)
{
    int g = blockIdx.x * blockDim.x + threadIdx.x;
    int total = B * nch * D;
    if (g >= total) return;
    int d = g % D;
    int ch = (g / D) % nch;
    int b = g / (D * nch);
    long base = ((long)b * S + (long)ch * L) * D + d;
    float h = g_hin[g];
#pragma unroll 4
    for (int i = 0; i < 128; i++) {
        float2 t = __half22float2(g_cv[base + (long)i * D]);
        h = fmaf(t.x, h, t.y);
        g_h[base + (long)i * D] = __float2half_rn(h);
    }
}

// ---------------- launch ----------------------------------------------------
extern "C" void kernel_launch(void* const* d_in, const int* in_sizes, int n_in,
                              void* d_out, int out_size)
{
    const float* inputs   = (const float*)d_in[0];
    // d_in[1]: attention_mask (unused by reference)
    const float* state    = (const float*)d_in[2];
    const float* normw    = (const float*)d_in[3];
    const float* router_w = (const float*)d_in[4];
    const float* w_in     = (const float*)d_in[5];
    const float* w_out    = (const float*)d_in[6];
    float* out = (float*)d_out;

    const int D = in_sizes[3];
    const int E = in_sizes[4] / D;
    const int B = in_sizes[2] / D;
    const int S = in_sizes[0] / (B * D);
    const int N2 = 2 * D;
    const int L = S / NCH;

    __half *px, *ph, *pWi, *pWo;
    __half2 *pcv;
    cudaGetSymbolAddress((void**)&px,  g_x);
    cudaGetSymbolAddress((void**)&pcv, g_cv);
    cudaGetSymbolAddress((void**)&ph,  g_h);
    cudaGetSymbolAddress((void**)&pWi, g_Wi);
    cudaGetSymbolAddress((void**)&pWo, g_Wo);

    cudaFuncSetAttribute(tc_gemm<0>, cudaFuncAttributeMaxDynamicSharedMemorySize, GEMM_SMEM);
    cudaFuncSetAttribute(tc_gemm<1>, cudaFuncAttributeMaxDynamicSharedMemorySize, GEMM_SMEM);

    // 1. RMSNorm (fp16 output)
    rmsnorm_kernel<<<B * S, 256>>>(inputs, normw, D);

    // 2. column partial sums
    {
        int total = PPART * B * D;
        colsum_partial_kernel<<<(total + 255) / 256, 256>>>(B, S, D);
    }

    // 3. fused colsum-final + router softmax
    router_fused_kernel<<<1, 1024>>>(router_w, B, S, D, E);

    // 4. expert-mixed transposed weights (fp16, all batches per tile)
    {
        dim3 gI(D / 32, N2 / 32);
        combineT_kernel<<<gI, 256>>>(w_in, pWi, B, E, D, N2, 1, D);   // interleaved
        dim3 gO(D / 32, D / 32);
        combineT_kernel<<<gO, 256>>>(w_out, pWo, B, E, D, D, 0, D);
    }

    // 5. GEMM1 (M=S, N=2D, K=D) with fused gating -> packed (c,v) in g_cv
    {
        dim3 grid(N2 / CTA_N, S / CTA_M, B);
        tc_gemm<1><<<grid, 256, GEMM_SMEM>>>(px, pWi, nullptr, nullptr,
                                             pcv,
                                             S, N2, D,
                                             (long)S * D, (long)N2 * D, 0L,
                                             D, S);
    }

    // 6. chunked scan
    {
        int totA = B * NCH * D;
        scan_passA_kernel<<<(totA + 255) / 256, 256>>>(B, S, D, L, NCH);
        scan_passB_kernel<<<(B * D + 255) / 256, 256>>>(state, out, B, D, NCH,
                                                        (long)B * S * D, (long)out_size);
        scan_passC_kernel<<<(totA + 255) / 256, 256>>>(B, S, D, L, NCH);
    }

    // 7. GEMM2: out = h @ Wo^T + inputs   (M=S, N=D, K=D)
    {
        dim3 grid(D / CTA_N, S / CTA_M, B);
        tc_gemm<0><<<grid, 256, GEMM_SMEM>>>(ph, pWo, inputs, out,
                                             nullptr,
                                             S, D, D,
                                             (long)S * D, (long)D * D, (long)S * D,
                                             D, S);
    }
}